// round 3
// baseline (speedup 1.0000x reference)
#include <cuda_runtime.h>
#include <cuda_fp16.h>
#include <cstdint>

// Problem dims
static constexpr int M = 256;
static constexpr int K = 4096;
static constexpr int N = 8192;
static constexpr int KITERS = K / 64;     // 64 K-chunks of 64

// SMEM: [0,1024) unused header, then buf0: A(16KB)+B(16KB), buf1: A(16KB)+B(16KB)
static constexpr int SMEM_TOTAL = 1024 + 4 * 16384;   // 66560

// fp16 x scratch (graph-safe: static __device__ array, no allocation)
__device__ __half g_xh[M * K];

// ---------------- helpers ----------------

__device__ __forceinline__ uint32_t smem_u32(const void* p) {
    uint32_t a;
    asm("{ .reg .u64 t; cvta.to.shared.u64 t, %1; cvt.u32.u64 %0, t; }"
        : "=r"(a) : "l"(p));
    return a;
}

__device__ __forceinline__ uint32_t sw128(uint32_t off) {
    return off ^ ((off >> 3) & 0x70);
}

// Dequant one 16-weight group (4 int32, low byte each = 4 x 2-bit codes)
// into 8 u32 = 16 fp16, via a 4-entry fp16 LUT + PRMT byte gather.
// n (fp32) is the group normalization; codes map to {-n, -n/3, +n/3, +n}.
__device__ __forceinline__ void dequant16(const int4& p4, float n, uint32_t o[8]) {
    uint32_t b1 = (uint32_t)__half_as_ushort(__float2half_rn(n));
    uint32_t b3 = (uint32_t)__half_as_ushort(__float2half_rn(n * (1.0f / 3.0f)));
    uint32_t loT = (b1 ^ 0x8000u) | ((b3 ^ 0x8000u) << 16);  // bytes: [-n][-n/3]
    uint32_t hiT = b3 | (b1 << 16);                          // bytes: [n/3][n]
    uint32_t pv[4] = { (uint32_t)p4.x, (uint32_t)p4.y, (uint32_t)p4.z, (uint32_t)p4.w };
    #pragma unroll
    for (int q = 0; q < 4; ++q) {
        uint32_t by = pv[q] & 0xFFu;   // 4 x 2-bit codes
        uint32_t l = by & 0xFu;        // codes u0 (bits1:0), u1 (bits3:2)
        uint32_t h = by >> 4;          // codes u2, u3
        // PRMT ctrl nibbles select bytes (2u, 2u+1) for each fp16
        uint32_t c0 = (l & 3u) * 0x22u + (l & 0xCu) * 0x880u + 0x1010u;
        uint32_t c1 = (h & 3u) * 0x22u + (h & 0xCu) * 0x880u + 0x1010u;
        o[2 * q]     = __byte_perm(loT, hiT, c0);
        o[2 * q + 1] = __byte_perm(loT, hiT, c1);
    }
}

// ---------------- kernel 0: x fp32 -> fp16 ----------------

__global__ void convert_x_kernel(const float* __restrict__ x) {
    int i = blockIdx.x * blockDim.x + threadIdx.x;     // float4 index
    float4 v = reinterpret_cast<const float4*>(x)[i];
    __half2* dst = reinterpret_cast<__half2*>(g_xh);
    dst[2 * i]     = __floats2half2_rn(v.x, v.y);
    dst[2 * i + 1] = __floats2half2_rn(v.z, v.w);
}

// ---------------- kernel 1: fused dequant + fp16 HMMA GEMM ----------------
// Grid (64, 2): blockIdx.x = N-tile (128 cols), blockIdx.y = M-tile (128 rows)
// 256 threads = 8 warps as 2(M) x 4(N); each warp owns 64x32 of the 128x128 tile.
// Per K-iter (BK=64): stage A [128x64 fp16] + dequant B [128x64 fp16] into SMEM
// (SW128 swizzled), 4 k-steps of ldmatrix.x4 + 16 mma.m16n8k16 per warp.
// Double buffered: LDGs for it+1 issue before MMAs of it; STS after; 1 barrier/iter.

__global__ void __launch_bounds__(256, 1)
linear2bit_gemm(const int4* __restrict__ wq,        // one int4 = one 16-value group
                const void* __restrict__ wn_raw,    // [NUM_GROUPS] norms (fp32 or fp16)
                const float* __restrict__ bias,     // [N]
                float* __restrict__ out)            // [M, N]
{
    extern __shared__ char smem[];
    const uint32_t sb = smem_u32(smem);
    const int tid = threadIdx.x;
    const int wid = tid >> 5;
    const int lid = tid & 31;
    const int ntile = blockIdx.x;
    const int mtile = blockIdx.y;

    // ---- runtime dtype probe for weight_norm ----
    // True fp32 delivery: element 0 in (6e-5, 0.06).
    // fp16 packed pair read as fp32: exponent bits come from a tiny fp16 -> ~1e-34.
    const float* wnf = (const float*)wn_raw;
    const __half* wnh = (const __half*)wn_raw;
    const float probe = __ldg(wnf);
    const bool norm_f32 = (probe > 6e-5f && probe < 0.06f);

    const int warp_m = wid & 1;      // 2 x 64 rows
    const int warp_n = wid >> 1;     // 4 x 32 cols

    const __half* xrow = g_xh + (size_t)(mtile * 128) * K;

    // Per-lane unswizzled smem byte bases for ldmatrix.x4 (k-step offset added later).
    // lanes 0-15 -> rows 0-15 @ k0-7 (byte 0), lanes 16-31 -> rows 0-15 @ k8-15 (+16B).
    uint32_t arow[4], brow[2];
    #pragma unroll
    for (int mt = 0; mt < 4; ++mt)
        arow[mt] = (uint32_t)((warp_m * 64 + mt * 16 + (lid & 15)) * 128 + (lid >> 4) * 16);
    #pragma unroll
    for (int p = 0; p < 2; ++p)
        brow[p] = (uint32_t)((warp_n * 32 + p * 16 + (lid & 15)) * 128 + (lid >> 4) * 16);

    float acc[4][4][4];
    #pragma unroll
    for (int mt = 0; mt < 4; ++mt)
        #pragma unroll
        for (int nt = 0; nt < 4; ++nt)
            #pragma unroll
            for (int e = 0; e < 4; ++e) acc[mt][nt][e] = 0.0f;

    int4  av[4];
    int4  bv[2];
    float bn[2];

    // ---- global prefetch for iteration `it` into registers ----
    auto ldg_tile = [&](int it) {
        #pragma unroll
        for (int i = 0; i < 4; ++i) {
            int idx = tid + 256 * i;
            int r = idx >> 3;
            int c = idx & 7;
            av[i] = __ldg(reinterpret_cast<const int4*>(xrow + (size_t)r * K + it * 64) + c);
        }
        #pragma unroll
        for (int i = 0; i < 2; ++i) {
            int gi = tid + 256 * i;
            int r = gi >> 2;
            int j = gi & 3;
            int gidx = (ntile * 128 + r) * 256 + it * 4 + j;
            bv[i] = __ldg(wq + gidx);
            bn[i] = norm_f32 ? __ldg(wnf + gidx)
                             : __half2float(__ldg(wnh + gidx));
        }
    };

    // ---- dequant + store prefetched registers into smem buffer b ----
    auto sts_tile = [&](int b) {
        char* abuf = smem + 1024 + b * 32768;
        char* bbuf = abuf + 16384;
        #pragma unroll
        for (int i = 0; i < 4; ++i) {
            int idx = tid + 256 * i;
            int r = idx >> 3;
            int c = idx & 7;
            *reinterpret_cast<int4*>(abuf + sw128((uint32_t)(r * 128 + c * 16))) = av[i];
        }
        #pragma unroll
        for (int i = 0; i < 2; ++i) {
            int gi = tid + 256 * i;
            int r = gi >> 2;
            int j = gi & 3;
            uint32_t o[8];
            dequant16(bv[i], bn[i], o);
            uint32_t off = (uint32_t)(r * 128 + j * 32);
            *reinterpret_cast<int4*>(bbuf + sw128(off)) =
                make_int4((int)o[0], (int)o[1], (int)o[2], (int)o[3]);
            *reinterpret_cast<int4*>(bbuf + sw128(off + 16)) =
                make_int4((int)o[4], (int)o[5], (int)o[6], (int)o[7]);
        }
    };

    ldg_tile(0);
    sts_tile(0);
    __syncthreads();

    #pragma unroll 2
    for (int it = 0; it < KITERS; ++it) {
        const int b = it & 1;
        if (it + 1 < KITERS) ldg_tile(it + 1);

        const uint32_t ab = sb + 1024u + (uint32_t)b * 32768u;
        const uint32_t bb = ab + 16384u;

        #pragma unroll
        for (int ks = 0; ks < 4; ++ks) {
            const uint32_t kb = (uint32_t)(ks * 32);   // 16 halves per k-step
            uint32_t af[4][4];
            uint32_t bf[2][4];
            #pragma unroll
            for (int mt = 0; mt < 4; ++mt) {
                uint32_t addr = ab + sw128(arow[mt] + kb);
                asm volatile(
                    "ldmatrix.sync.aligned.m8n8.x4.shared.b16 {%0,%1,%2,%3}, [%4];"
                    : "=r"(af[mt][0]), "=r"(af[mt][1]), "=r"(af[mt][2]), "=r"(af[mt][3])
                    : "r"(addr));
            }
            #pragma unroll
            for (int p = 0; p < 2; ++p) {
                uint32_t addr = bb + sw128(brow[p] + kb);
                asm volatile(
                    "ldmatrix.sync.aligned.m8n8.x4.shared.b16 {%0,%1,%2,%3}, [%4];"
                    : "=r"(bf[p][0]), "=r"(bf[p][1]), "=r"(bf[p][2]), "=r"(bf[p][3])
                    : "r"(addr));
            }
            #pragma unroll
            for (int mt = 0; mt < 4; ++mt) {
                #pragma unroll
                for (int nt = 0; nt < 4; ++nt) {
                    uint32_t b0 = bf[nt >> 1][nt & 1];
                    uint32_t b1 = bf[nt >> 1][(nt & 1) + 2];
                    asm volatile(
                        "mma.sync.aligned.m16n8k16.row.col.f32.f16.f16.f32 "
                        "{%0,%1,%2,%3}, {%4,%5,%6,%7}, {%8,%9}, {%0,%1,%2,%3};"
                        : "+f"(acc[mt][nt][0]), "+f"(acc[mt][nt][1]),
                          "+f"(acc[mt][nt][2]), "+f"(acc[mt][nt][3])
                        : "r"(af[mt][0]), "r"(af[mt][1]), "r"(af[mt][2]), "r"(af[mt][3]),
                          "r"(b0), "r"(b1));
                }
            }
        }

        if (it + 1 < KITERS) sts_tile(b ^ 1);
        __syncthreads();
    }

    // ---- epilogue: write accumulators + bias ----
    {
        const int mbase = mtile * 128 + warp_m * 64;
        const int nbase = ntile * 128 + warp_n * 32;
        const int rq = lid >> 2;             // row within m16 (0..7)
        const int cq = (lid & 3) * 2;        // col within n8 (0,2,4,6)
        #pragma unroll
        for (int mt = 0; mt < 4; ++mt) {
            #pragma unroll
            for (int nt = 0; nt < 4; ++nt) {
                int m0 = mbase + mt * 16 + rq;
                int n0 = nbase + nt * 8 + cq;
                float2 bsv = __ldg(reinterpret_cast<const float2*>(bias + n0));
                float2 v0, v1;
                v0.x = acc[mt][nt][0] + bsv.x;
                v0.y = acc[mt][nt][1] + bsv.y;
                v1.x = acc[mt][nt][2] + bsv.x;
                v1.y = acc[mt][nt][3] + bsv.y;
                *reinterpret_cast<float2*>(out + (size_t)m0 * N + n0) = v0;
                *reinterpret_cast<float2*>(out + (size_t)(m0 + 8) * N + n0) = v1;
            }
        }
    }
}

// ---------------- launch ----------------

extern "C" void kernel_launch(void* const* d_in, const int* in_sizes, int n_in,
                              void* d_out, int out_size) {
    (void)in_sizes; (void)n_in; (void)out_size;
    const float* x    = (const float*)d_in[0];
    const int4*  wq   = (const int4*)d_in[1];    // [NUM_GROUPS] groups of 4 int32
    const void*  wn   = (const void*)d_in[2];    // [NUM_GROUPS] norms (fp32 or fp16)
    const float* bias = (const float*)d_in[3];
    float*       out  = (float*)d_out;

    cudaFuncSetAttribute(linear2bit_gemm,
                         cudaFuncAttributeMaxDynamicSharedMemorySize, SMEM_TOTAL);

    convert_x_kernel<<<(M * K / 4) / 256, 256>>>(x);
    linear2bit_gemm<<<dim3(N / 128, M / 128), 256, SMEM_TOTAL>>>(wq, wn, bias, out);
}

// round 4
// speedup vs baseline: 1.1074x; 1.1074x over previous
#include <cuda_runtime.h>
#include <cuda_fp16.h>
#include <cstdint>

// Problem dims
static constexpr int M = 256;
static constexpr int K = 4096;
static constexpr int N = 8192;
static constexpr int KITERS = K / 64;     // 64 K-chunks of 64

// SMEM: [0,1024) header (unused), then B double buffer: 2 x (64 rows x 128B)
static constexpr int SMEM_TOTAL = 1024 + 2 * 8192;   // 17408

// A in m16n8k16 fragment layout, fp16, built by convert kernel.
// Index: ((mi * (K/16) + ki) * 32 + lane) -> uint4 (regs a0,a1,a2,a3)
__device__ uint4 g_xa[(M / 16) * (K / 16) * 32];

// ---------------- helpers ----------------

__device__ __forceinline__ uint32_t smem_u32(const void* p) {
    uint32_t a;
    asm("{ .reg .u64 t; cvta.to.shared.u64 t, %1; cvt.u32.u64 %0, t; }"
        : "=r"(a) : "l"(p));
    return a;
}

__device__ __forceinline__ uint32_t sw128(uint32_t off) {
    return off ^ ((off >> 3) & 0x70);
}

// Dequant one 16-weight group (4 int32, low byte each = 4 x 2-bit codes)
// into 8 u32 = 16 fp16, via a 4-entry fp16 LUT + PRMT byte gather.
__device__ __forceinline__ void dequant16(const int4& p4, float n, uint32_t o[8]) {
    uint32_t b1 = (uint32_t)__half_as_ushort(__float2half_rn(n));
    uint32_t b3 = (uint32_t)__half_as_ushort(__float2half_rn(n * (1.0f / 3.0f)));
    uint32_t loT = (b1 ^ 0x8000u) | ((b3 ^ 0x8000u) << 16);  // bytes: [-n][-n/3]
    uint32_t hiT = b3 | (b1 << 16);                          // bytes: [n/3][n]
    uint32_t pv[4] = { (uint32_t)p4.x, (uint32_t)p4.y, (uint32_t)p4.z, (uint32_t)p4.w };
    #pragma unroll
    for (int q = 0; q < 4; ++q) {
        uint32_t by = pv[q] & 0xFFu;   // 4 x 2-bit codes
        uint32_t l = by & 0xFu;
        uint32_t h = by >> 4;
        uint32_t c0 = (l & 3u) * 0x22u + (l & 0xCu) * 0x880u + 0x1010u;
        uint32_t c1 = (h & 3u) * 0x22u + (h & 0xCu) * 0x880u + 0x1010u;
        o[2 * q]     = __byte_perm(loT, hiT, c0);
        o[2 * q + 1] = __byte_perm(loT, hiT, c1);
    }
}

// ---------------- kernel 0: x fp32 -> A-fragment fp16 layout ----------------
// One thread builds one lane-fragment (uint4) of one m16k16 tile:
//   a0 = (r, c),(r, c+1)   a1 = (r+8, c),(r+8, c+1)
//   a2 = (r, c+8),(r,c+9)  a3 = (r+8, c+8),(r+8, c+9)
// with r = lane>>2, c = (lane&3)*2.

__global__ void convert_x_frag(const float* __restrict__ x) {
    int g = blockIdx.x * blockDim.x + threadIdx.x;   // 0 .. 131071
    int lane = g & 31;
    int ki = (g >> 5) & (K / 16 - 1);
    int mi = g >> 13;
    int r = lane >> 2;
    int c = (lane & 3) * 2;
    const float* base = x + (size_t)(mi * 16 + r) * K + ki * 16 + c;
    float2 v00 = *reinterpret_cast<const float2*>(base);
    float2 v10 = *reinterpret_cast<const float2*>(base + 8 * K);
    float2 v01 = *reinterpret_cast<const float2*>(base + 8);
    float2 v11 = *reinterpret_cast<const float2*>(base + 8 * K + 8);
    uint4 o;
    o.x = (uint32_t)__half_as_ushort(__float2half_rn(v00.x)) |
          ((uint32_t)__half_as_ushort(__float2half_rn(v00.y)) << 16);
    o.y = (uint32_t)__half_as_ushort(__float2half_rn(v10.x)) |
          ((uint32_t)__half_as_ushort(__float2half_rn(v10.y)) << 16);
    o.z = (uint32_t)__half_as_ushort(__float2half_rn(v01.x)) |
          ((uint32_t)__half_as_ushort(__float2half_rn(v01.y)) << 16);
    o.w = (uint32_t)__half_as_ushort(__float2half_rn(v11.x)) |
          ((uint32_t)__half_as_ushort(__float2half_rn(v11.y)) << 16);
    g_xa[g] = o;
}

// ---------------- kernel 1: fused dequant + fp16 HMMA GEMM ----------------
// Grid (128, 2): blockIdx.x = N-tile (64 cols), blockIdx.y = M-tile (128 rows)
// 256 threads = 8 warps as 4(M) x 2(N); warp tile 32x32 (mt=2, nt=4).
// A: direct LDG.128 of pre-built fragments (no SMEM). B: dequant -> SMEM
// (SW128) -> ldmatrix, double buffered, 1 barrier per K-iter.

__global__ void __launch_bounds__(256, 2)
linear2bit_gemm(const int4* __restrict__ wq,        // one int4 = one 16-value group
                const void* __restrict__ wn_raw,    // [NUM_GROUPS] norms (fp32 or fp16)
                const float* __restrict__ bias,     // [N]
                float* __restrict__ out)            // [M, N]
{
    extern __shared__ char smem[];
    const uint32_t sb = smem_u32(smem);
    const int tid = threadIdx.x;
    const int wid = tid >> 5;
    const int lid = tid & 31;
    const int ntile = blockIdx.x;                   // 64-col tile
    const int mtile = blockIdx.y;                   // 128-row tile

    // ---- runtime dtype probe for weight_norm (fp32 confirmed; probe kept) ----
    const float* wnf = (const float*)wn_raw;
    const __half* wnh = (const __half*)wn_raw;
    const float probe = __ldg(wnf);
    const bool norm_f32 = (probe > 6e-5f && probe < 0.06f);

    const int warp_m = wid >> 1;     // 4 x 32 rows
    const int warp_n = wid & 1;      // 2 x 32 cols

    // B ldmatrix per-lane unswizzled bases (two 16-row groups per warp)
    uint32_t brow[2];
    #pragma unroll
    for (int p = 0; p < 2; ++p)
        brow[p] = (uint32_t)((warp_n * 32 + p * 16 + (lid & 15)) * 128 + (lid >> 4) * 16);

    // A fragment gmem base: mi = mtile*8 + warp_m*2 + mt, ki = it*4 + ks
    const uint4* afrag = g_xa + ((size_t)(mtile * 8 + warp_m * 2) * (K / 16)) * 32 + lid;

    float acc[2][4][4];
    #pragma unroll
    for (int mt = 0; mt < 2; ++mt)
        #pragma unroll
        for (int nt = 0; nt < 4; ++nt)
            #pragma unroll
            for (int e = 0; e < 4; ++e) acc[mt][nt][e] = 0.0f;

    // B staging: 1 group per thread per iter (64 rows x 4 groups = 256)
    const int br = tid >> 2;        // B row in tile (0..63)
    const int bj = tid & 3;         // group within K-chunk (0..3)
    const int bg_base = (ntile * 64 + br) * 256 + bj;   // + it*4

    int4  bv;
    float bn;

    auto ldg_b = [&](int it) {
        int gidx = bg_base + it * 4;
        bv = __ldg(wq + gidx);
        bn = norm_f32 ? __ldg(wnf + gidx) : __half2float(__ldg(wnh + gidx));
    };
    auto sts_b = [&](int b) {
        char* bbuf = smem + 1024 + b * 8192;
        uint32_t o[8];
        dequant16(bv, bn, o);
        uint32_t off = (uint32_t)(br * 128 + bj * 32);
        *reinterpret_cast<int4*>(bbuf + sw128(off)) =
            make_int4((int)o[0], (int)o[1], (int)o[2], (int)o[3]);
        *reinterpret_cast<int4*>(bbuf + sw128(off + 16)) =
            make_int4((int)o[4], (int)o[5], (int)o[6], (int)o[7]);
    };

    ldg_b(0);
    sts_b(0);
    __syncthreads();

    #pragma unroll 1
    for (int it = 0; it < KITERS; ++it) {
        const int b = it & 1;
        if (it + 1 < KITERS) ldg_b(it + 1);

        // Prefetch all A fragments for this iter (8 coalesced LDG.128 / warp)
        uint4 af[2][4];
        #pragma unroll
        for (int mt = 0; mt < 2; ++mt)
            #pragma unroll
            for (int ks = 0; ks < 4; ++ks)
                af[mt][ks] = __ldg(afrag + ((size_t)mt * (K / 16) + it * 4 + ks) * 32);

        const uint32_t bb = sb + 1024u + (uint32_t)b * 8192u;

        #pragma unroll
        for (int ks = 0; ks < 4; ++ks) {
            const uint32_t kb = (uint32_t)(ks * 32);   // 16 halves per k-step
            uint32_t bf[2][4];
            #pragma unroll
            for (int p = 0; p < 2; ++p) {
                uint32_t addr = bb + sw128(brow[p] + kb);
                asm volatile(
                    "ldmatrix.sync.aligned.m8n8.x4.shared.b16 {%0,%1,%2,%3}, [%4];"
                    : "=r"(bf[p][0]), "=r"(bf[p][1]), "=r"(bf[p][2]), "=r"(bf[p][3])
                    : "r"(addr));
            }
            #pragma unroll
            for (int mt = 0; mt < 2; ++mt) {
                #pragma unroll
                for (int nt = 0; nt < 4; ++nt) {
                    uint32_t b0 = bf[nt >> 1][nt & 1];
                    uint32_t b1 = bf[nt >> 1][(nt & 1) + 2];
                    asm volatile(
                        "mma.sync.aligned.m16n8k16.row.col.f32.f16.f16.f32 "
                        "{%0,%1,%2,%3}, {%4,%5,%6,%7}, {%8,%9}, {%0,%1,%2,%3};"
                        : "+f"(acc[mt][nt][0]), "+f"(acc[mt][nt][1]),
                          "+f"(acc[mt][nt][2]), "+f"(acc[mt][nt][3])
                        : "r"(af[mt][ks].x), "r"(af[mt][ks].y),
                          "r"(af[mt][ks].z), "r"(af[mt][ks].w),
                          "r"(b0), "r"(b1));
                }
            }
        }

        if (it + 1 < KITERS) sts_b(b ^ 1);
        __syncthreads();
    }

    // ---- epilogue: write accumulators + bias ----
    {
        const int mbase = mtile * 128 + warp_m * 32;
        const int nbase = ntile * 64 + warp_n * 32;
        const int rq = lid >> 2;             // row within m16 (0..7)
        const int cq = (lid & 3) * 2;        // col within n8 (0,2,4,6)
        #pragma unroll
        for (int mt = 0; mt < 2; ++mt) {
            #pragma unroll
            for (int nt = 0; nt < 4; ++nt) {
                int m0 = mbase + mt * 16 + rq;
                int n0 = nbase + nt * 8 + cq;
                float2 bsv = __ldg(reinterpret_cast<const float2*>(bias + n0));
                float2 v0, v1;
                v0.x = acc[mt][nt][0] + bsv.x;
                v0.y = acc[mt][nt][1] + bsv.y;
                v1.x = acc[mt][nt][2] + bsv.x;
                v1.y = acc[mt][nt][3] + bsv.y;
                *reinterpret_cast<float2*>(out + (size_t)m0 * N + n0) = v0;
                *reinterpret_cast<float2*>(out + (size_t)(m0 + 8) * N + n0) = v1;
            }
        }
    }
}

// ---------------- launch ----------------

extern "C" void kernel_launch(void* const* d_in, const int* in_sizes, int n_in,
                              void* d_out, int out_size) {
    (void)in_sizes; (void)n_in; (void)out_size;
    const float* x    = (const float*)d_in[0];
    const int4*  wq   = (const int4*)d_in[1];    // [NUM_GROUPS] groups of 4 int32
    const void*  wn   = (const void*)d_in[2];    // [NUM_GROUPS] norms
    const float* bias = (const float*)d_in[3];
    float*       out  = (float*)d_out;

    cudaFuncSetAttribute(linear2bit_gemm,
                         cudaFuncAttributeMaxDynamicSharedMemorySize, SMEM_TOTAL);

    convert_x_frag<<<(M / 16) * (K / 16) * 32 / 256, 256>>>(x);
    linear2bit_gemm<<<dim3(N / 64, M / 128), 256, SMEM_TOTAL>>>(wq, wn, bias, out);
}